// round 1
// baseline (speedup 1.0000x reference)
#include <cuda_runtime.h>
#include <math.h>

#define NTOK 16384
#define DDIM 2048
#define NEXP 64
#define TM   128
#define NBLK (NTOK / TM)      // 128 blocks
#define KC   32
#define NCHUNK (DDIM / KC)    // 64 chunks
#define NOISE_STD (1.0f / 64.0f)

// Deterministic scratch for cross-block reductions (no cudaMalloc allowed).
__device__ float g_part_imp[NBLK][NEXP];
__device__ float g_part_p[NBLK][NEXP];

// ---- packed f32x2 helpers (sm_103a FFMA2 path) ----
__device__ __forceinline__ unsigned long long pack2_dup(float v) {
    unsigned long long r;
    unsigned int u = __float_as_uint(v);
    asm("mov.b64 %0, {%1, %2};" : "=l"(r) : "r"(u), "r"(u));
    return r;
}
__device__ __forceinline__ unsigned long long fma2(unsigned long long a,
                                                   unsigned long long b,
                                                   unsigned long long c) {
    unsigned long long d;
    asm("fma.rn.f32x2 %0, %1, %2, %3;" : "=l"(d) : "l"(a), "l"(b), "l"(c));
    return d;
}
__device__ __forceinline__ void unpack2(unsigned long long v, float& lo, float& hi) {
    unsigned int a, b;
    asm("mov.b64 {%0, %1}, %2;" : "=r"(a), "=r"(b) : "l"(v));
    lo = __uint_as_float(a);
    hi = __uint_as_float(b);
}

// value-then-lower-index "greater" comparator (matches lax.top_k tie order)
__device__ __forceinline__ bool gtv(float a, int ia, float b, int ib) {
    return (a > b) || (a == b && ia < ib);
}

__global__ void __launch_bounds__(128)
router_main(const float* __restrict__ x, const float* __restrict__ W,
            const float* __restrict__ bias_g, const float* __restrict__ noise,
            float* __restrict__ out) {
    // smem: GEMM phase uses As[KC][TM] (4096 f) + Bs[KC][NEXP] (2048 f) = 6144 f.
    // Epilogue phase reuses it as Ls[TM][66] = 8448 f (66 stride -> 8B-aligned float2 rows).
    __shared__ __align__(16) float sm[TM * 66];
    float* As = sm;            // [KC][TM]
    float* Bs = sm + KC * TM;  // [KC][NEXP]

    const int tid = threadIdx.x;
    const int bm  = blockIdx.x * TM;
    const int tn  = tid & 7;    // 0..7  (expert group of 8)
    const int tm  = tid >> 3;   // 0..15 (token group of 8)

    // ---- GEMM: C[128 tokens][64 experts], 8x8 micro-tile, f32x2 packed over token pairs
    unsigned long long acc[4][8];
#pragma unroll
    for (int i = 0; i < 4; i++)
#pragma unroll
        for (int j = 0; j < 8; j++) acc[i][j] = 0ull;

    const float* xp = x + (size_t)(bm + tid) * DDIM;  // this thread's token row
    const int wr = tid >> 4;          // 0..7
    const int wc = (tid & 15) * 4;    // 0..60

    float4 xr[8];
    float4 wg[4];
#pragma unroll
    for (int i = 0; i < 8; i++) xr[i] = *(const float4*)(xp + i * 4);
#pragma unroll
    for (int i = 0; i < 4; i++)
        wg[i] = *(const float4*)(W + (size_t)(wr + 8 * i) * NEXP + wc);

    for (int c = 0; c < NCHUNK; ++c) {
        __syncthreads();
        // stage chunk into smem (x transposed to [k][m])
#pragma unroll
        for (int i = 0; i < 8; i++) {
            As[(i * 4 + 0) * TM + tid] = xr[i].x;
            As[(i * 4 + 1) * TM + tid] = xr[i].y;
            As[(i * 4 + 2) * TM + tid] = xr[i].z;
            As[(i * 4 + 3) * TM + tid] = xr[i].w;
        }
#pragma unroll
        for (int i = 0; i < 4; i++)
            *(float4*)(Bs + (wr + 8 * i) * NEXP + wc) = wg[i];
        __syncthreads();

        // prefetch next chunk into registers (overlaps with compute)
        if (c + 1 < NCHUNK) {
            const float* xn = xp + (c + 1) * KC;
#pragma unroll
            for (int i = 0; i < 8; i++) xr[i] = *(const float4*)(xn + i * 4);
#pragma unroll
            for (int i = 0; i < 4; i++)
                wg[i] = *(const float4*)(W + (size_t)((c + 1) * KC + wr + 8 * i) * NEXP + wc);
        }

#pragma unroll 8
        for (int k = 0; k < KC; ++k) {
            const ulonglong2 A0 = *(const ulonglong2*)(As + k * TM + tm * 8);
            const ulonglong2 A1 = *(const ulonglong2*)(As + k * TM + tm * 8 + 4);
            unsigned long long ap[4] = {A0.x, A0.y, A1.x, A1.y};
            const float4 B0 = *(const float4*)(Bs + k * NEXP + tn * 8);
            const float4 B1 = *(const float4*)(Bs + k * NEXP + tn * 8 + 4);
            const float bv[8] = {B0.x, B0.y, B0.z, B0.w, B1.x, B1.y, B1.z, B1.w};
#pragma unroll
            for (int ni = 0; ni < 8; ni++) {
                const unsigned long long bb = pack2_dup(bv[ni]);
#pragma unroll
                for (int mi = 0; mi < 4; mi++)
                    acc[mi][ni] = fma2(ap[mi], bb, acc[mi][ni]);
            }
        }
    }

    // ---- stage logits (+bias) into Ls[t_local][e], stride 66
    __syncthreads();
    float bv8[8];
#pragma unroll
    for (int j = 0; j < 8; j++) bv8[j] = __ldg(bias_g + tn * 8 + j);
#pragma unroll
    for (int mi = 0; mi < 4; mi++) {
#pragma unroll
        for (int ni = 0; ni < 8; ni++) {
            float lo, hi;
            unpack2(acc[mi][ni], lo, hi);
            const int e = tn * 8 + ni;
            sm[(tm * 8 + 2 * mi + 0) * 66 + e] = lo + bv8[ni];
            sm[(tm * 8 + 2 * mi + 1) * 66 + e] = hi + bv8[ni];
        }
    }
    __syncthreads();

    // ---- per-token epilogue: warp wp handles tokens [wp*32, wp*32+32)
    const int lane = tid & 31;
    const int wp   = tid >> 5;
    const int e0   = 2 * lane;
    const int e1   = 2 * lane + 1;

    float imp0 = 0.f, imp1 = 0.f, pa0 = 0.f, pa1 = 0.f;

    for (int tt = 0; tt < 32; ++tt) {
        const int tl = wp * 32 + tt;
        const int t  = bm + tl;
        const float2 L2 = *(const float2*)(sm + tl * 66 + e0);
        const float l0 = L2.x, l1 = L2.y;

        // clean softmax (for importance)
        float mx = fmaxf(l0, l1);
#pragma unroll
        for (int off = 16; off; off >>= 1)
            mx = fmaxf(mx, __shfl_xor_sync(0xffffffffu, mx, off));
        const float s0 = __expf(l0 - mx);
        const float s1 = __expf(l1 - mx);
        float ss = s0 + s1;
#pragma unroll
        for (int off = 16; off; off >>= 1)
            ss += __shfl_xor_sync(0xffffffffu, ss, off);
        const float rs = 1.0f / ss;
        imp0 += s0 * rs;
        imp1 += s1 * rs;

        // noisy logits + warp top-2 (value desc, lower index on ties)
        const float2 nz = *(const float2*)(noise + (size_t)t * NEXP + e0);
        const float n0 = fmaf(NOISE_STD, nz.x, l0);
        const float n1 = fmaf(NOISE_STD, nz.y, l1);
        float v1, v2;
        int i1, i2;
        if (n0 >= n1) { v1 = n0; i1 = e0; v2 = n1; i2 = e1; }
        else          { v1 = n1; i1 = e1; v2 = n0; i2 = e0; }
#pragma unroll
        for (int off = 16; off; off >>= 1) {
            const float ov1 = __shfl_xor_sync(0xffffffffu, v1, off);
            const int   oi1 = __shfl_xor_sync(0xffffffffu, i1, off);
            const float ov2 = __shfl_xor_sync(0xffffffffu, v2, off);
            const int   oi2 = __shfl_xor_sync(0xffffffffu, i2, off);
            if (gtv(ov1, oi1, v1, i1)) {
                if (gtv(v1, i1, ov2, oi2)) { v2 = v1; i2 = i1; }
                else                       { v2 = ov2; i2 = oi2; }
                v1 = ov1; i1 = oi1;
            } else if (gtv(ov1, oi1, v2, i2)) {
                v2 = ov1; i2 = oi1;
            }
        }

        // renormalized top-2 gate values: e1=1, e2=exp(v2-v1)
        const float ee = __expf(v2 - v1);
        const float g1 = 1.0f / (1.0f + ee);
        const float g2 = ee * g1;

        // load-loss probability: p = 1 - Phi((thr - logit)/noise_std) = Phi(-z)
        const float z0 = (v2 - l0) * 64.0f;
        const float z1 = (v2 - l1) * 64.0f;
        pa0 += normcdff(-z0);
        pa1 += normcdff(-z1);

        if (lane == 0) {
            out[2 * t + 0] = g1;
            out[2 * t + 1] = g2;
            out[2 * NTOK + 2 * t + 0] = (float)i1;
            out[2 * NTOK + 2 * t + 1] = (float)i2;
        }
    }

    // ---- deterministic block partials
    __syncthreads();  // all warps done reading Ls
    float* redI = sm;         // [4][64]
    float* redP = sm + 256;   // [4][64]
    redI[wp * 64 + e0] = imp0;
    redI[wp * 64 + e1] = imp1;
    redP[wp * 64 + e0] = pa0;
    redP[wp * 64 + e1] = pa1;
    __syncthreads();
    if (tid < NEXP) {
        g_part_imp[blockIdx.x][tid] =
            redI[tid] + redI[64 + tid] + redI[128 + tid] + redI[192 + tid];
        g_part_p[blockIdx.x][tid] =
            redP[tid] + redP[64 + tid] + redP[128 + tid] + redP[192 + tid];
    }
}

__global__ void router_reduce(float* __restrict__ out) {
    const int e = threadIdx.x;  // 0..63
    float si = 0.f, sp = 0.f;
    for (int b = 0; b < NBLK; ++b) {
        si += g_part_imp[b][e];
        sp += g_part_p[b][e];
    }
    __shared__ float sa[NEXP], sb[NEXP];
    sa[e] = si;
    sb[e] = sp * (1.0f / NTOK);  // p_mean
    __syncthreads();
    if (e == 0) {
        float ma = 0.f, mp = 0.f;
        for (int i = 0; i < NEXP; i++) { ma += sa[i]; mp += sb[i]; }
        ma *= (1.0f / NEXP);
        mp *= (1.0f / NEXP);
        float va = 0.f, vp = 0.f;
        for (int i = 0; i < NEXP; i++) {
            const float da = sa[i] - ma;
            const float dp = sb[i] - mp;
            va += da * da;
            vp += dp * dp;
        }
        va *= (1.0f / (NEXP - 1));  // ddof=1
        vp *= (1.0f / (NEXP - 1));
        const float il = va / ((ma + 1e-8f) * (ma + 1e-8f));
        const float ll = vp / ((mp + 1e-8f) * (mp + 1e-8f));
        out[4 * NTOK] = 0.5f * (il + ll);
    }
}

extern "C" void kernel_launch(void* const* d_in, const int* in_sizes, int n_in,
                              void* d_out, int out_size) {
    const float* x     = (const float*)d_in[0];
    const float* W     = (const float*)d_in[1];
    const float* b     = (const float*)d_in[2];
    const float* noise = (const float*)d_in[3];
    float* out = (float*)d_out;

    router_main<<<NBLK, 128>>>(x, W, b, noise, out);
    router_reduce<<<1, NEXP>>>(out);
}